// round 5
// baseline (speedup 1.0000x reference)
#include <cuda_runtime.h>
#include <cuda_fp16.h>
#include <stdint.h>

// Problem constants
#define B_BATCH 8
#define SEQ     4096
#define DIN     1024
#define DOUT    1024
#define RTOT    104

// Scratch: fp16 folded weights (16 MB) and fp16 x (64 MB)
__device__ __half g_wh[(size_t)B_BATCH * DOUT * DIN];
__device__ __half g_xh[(size_t)B_BATCH * SEQ * DIN];

__device__ __forceinline__ uint32_t smem_u32(const void* p) {
    return (uint32_t)__cvta_generic_to_shared(p);
}
__device__ __forceinline__ void cp_async16(uint32_t saddr, const void* gptr) {
    asm volatile("cp.async.cg.shared.global [%0], [%1], 16;\n" :: "r"(saddr), "l"(gptr));
}
__device__ __forceinline__ void cp_commit() {
    asm volatile("cp.async.commit_group;\n");
}
template <int N>
__device__ __forceinline__ void cp_wait() {
    asm volatile("cp.async.wait_group %0;\n" :: "n"(N));
}
__device__ __forceinline__ void ldmatrix_x4(uint32_t r[4], uint32_t addr) {
    asm volatile("ldmatrix.sync.aligned.m8n8.x4.shared.b16 {%0,%1,%2,%3}, [%4];"
                 : "=r"(r[0]), "=r"(r[1]), "=r"(r[2]), "=r"(r[3]) : "r"(addr));
}
__device__ __forceinline__ void ldmatrix_x4_trans(uint32_t r[4], uint32_t addr) {
    asm volatile("ldmatrix.sync.aligned.m8n8.x4.trans.shared.b16 {%0,%1,%2,%3}, [%4];"
                 : "=r"(r[0]), "=r"(r[1]), "=r"(r[2]), "=r"(r[3]) : "r"(addr));
}
// fp32-accum variant (used by prep kernel)
__device__ __forceinline__ void mma_f16(float c[4], const uint32_t a[4],
                                        uint32_t b0, uint32_t b1) {
    asm volatile("mma.sync.aligned.m16n8k16.row.col.f32.f16.f16.f32 "
                 "{%0,%1,%2,%3}, {%4,%5,%6,%7}, {%8,%9}, {%0,%1,%2,%3};\n"
                 : "+f"(c[0]), "+f"(c[1]), "+f"(c[2]), "+f"(c[3])
                 : "r"(a[0]), "r"(a[1]), "r"(a[2]), "r"(a[3]), "r"(b0), "r"(b1));
}
// fp16-accum variants (main gemm): d = a*b + 0  and  d = a*b + d
__device__ __forceinline__ void mma_h16_z(uint32_t& d0, uint32_t& d1,
                                          const uint32_t a[4], uint32_t b0, uint32_t b1) {
    asm volatile("mma.sync.aligned.m16n8k16.row.col.f16.f16.f16.f16 "
                 "{%0,%1}, {%2,%3,%4,%5}, {%6,%7}, {%8,%8};\n"
                 : "=r"(d0), "=r"(d1)
                 : "r"(a[0]), "r"(a[1]), "r"(a[2]), "r"(a[3]), "r"(b0), "r"(b1), "r"(0u));
}
__device__ __forceinline__ void mma_h16_acc(uint32_t& d0, uint32_t& d1,
                                            const uint32_t a[4], uint32_t b0, uint32_t b1) {
    asm volatile("mma.sync.aligned.m16n8k16.row.col.f16.f16.f16.f16 "
                 "{%0,%1}, {%2,%3,%4,%5}, {%6,%7}, {%0,%1};\n"
                 : "+r"(d0), "+r"(d1)
                 : "r"(a[0]), "r"(a[1]), "r"(a[2]), "r"(a[3]), "r"(b0), "r"(b1));
}

// ---------------------------------------------------------------------------
// x -> fp16 convert. 8*4096*1024 floats = 8.39M float4, one per thread.
// ---------------------------------------------------------------------------
__global__ __launch_bounds__(256) void conv_x_kernel(const float4* __restrict__ x4) {
    size_t i = (size_t)blockIdx.x * 256 + threadIdx.x;
    float4 v = x4[i];
    __half2* o = (__half2*)(g_xh + i * 4);
    o[0] = __floats2half2_rn(v.x, v.y);
    o[1] = __floats2half2_rn(v.z, v.w);
}

// ---------------------------------------------------------------------------
// Tensor-core prep (unchanged from round 4): W_eff[b] = base_w + pu_mod[b] @ pd.
// ---------------------------------------------------------------------------
#define KP 112
#define PSA 120
#define PSB 136
#define PREP_A_HALVES (128 * PSA)
#define PREP_SMEM_BYTES ((128 * PSA + KP * PSB) * 2)

__global__ __launch_bounds__(256) void prep_mma_kernel(
    const float* __restrict__ base_w,
    const float* __restrict__ pd_w,
    const float* __restrict__ pu_w,
    const float* __restrict__ mem_f,
    const float* __restrict__ mem_m,
    const float* __restrict__ mem_s)
{
    extern __shared__ __half psm[];
    __half* As = psm;
    __half* Bs = psm + PREP_A_HALVES;
    __shared__ float s_fac[KP];

    const int b  = blockIdx.z;
    const int o0 = blockIdx.y * 128;
    const int d0 = blockIdx.x * 128;
    const int tid = threadIdx.x;

    if (tid < KP) {
        float f = 0.0f;
        int r = tid;
        if (r < RTOT) {
            float memv;
            if (r < 8)       memv = mem_f[b * 8  + r];
            else if (r < 40) memv = mem_m[b * 32 + (r - 8)];
            else             memv = mem_s[b * 64 + (r - 40)];
            f = (1.0f + memv) * (1.0f / 3.0f);
        }
        s_fac[r] = f;
    }
    __syncthreads();

    for (int i = tid; i < 128 * KP; i += 256) {
        int o = i / KP, r = i - o * KP;
        float v = (r < RTOT) ? pu_w[(size_t)(o0 + o) * RTOT + r] * s_fac[r] : 0.0f;
        As[o * PSA + r] = __float2half(v);
    }
    for (int i = tid; i < KP * 128; i += 256) {
        int r = i >> 7, d = i & 127;
        float v = (r < RTOT) ? pd_w[(size_t)r * DIN + d0 + d] : 0.0f;
        Bs[r * PSB + d] = __float2half(v);
    }
    __syncthreads();

    const int lane = tid & 31;
    const int wid  = tid >> 5;
    const int wm   = wid >> 2;
    const int wn   = wid & 3;

    const int mi = lane >> 3;
    const int rl = lane & 7;
    const int aRow = wm * 64 + ((mi & 1) << 3) + rl;
    const int gsel = mi >> 1;
    const int bK   = ((mi >> 1) << 3) + rl;
    const int bN   = wn * 32 + ((mi & 1) << 3);

    const uint32_t sA = smem_u32(As);
    const uint32_t sB = smem_u32(Bs);

    float acc[4][4][4];
    #pragma unroll
    for (int mf = 0; mf < 4; mf++)
        #pragma unroll
        for (int nf = 0; nf < 4; nf++)
            #pragma unroll
            for (int k = 0; k < 4; k++) acc[mf][nf][k] = 0.0f;

    #pragma unroll
    for (int ks = 0; ks < KP / 16; ks++) {
        uint32_t a[4][4], bf[2][4];
        #pragma unroll
        for (int mf = 0; mf < 4; mf++)
            ldmatrix_x4(a[mf],
                sA + (uint32_t)(((aRow + mf * 16) * PSA + ks * 16 + gsel * 8) * 2));
        #pragma unroll
        for (int nfp = 0; nfp < 2; nfp++)
            ldmatrix_x4_trans(bf[nfp],
                sB + (uint32_t)(((ks * 16 + bK) * PSB + bN + nfp * 16) * 2));
        #pragma unroll
        for (int mf = 0; mf < 4; mf++)
            #pragma unroll
            for (int nfp = 0; nfp < 2; nfp++) {
                mma_f16(acc[mf][2 * nfp + 0], a[mf], bf[nfp][0], bf[nfp][2]);
                mma_f16(acc[mf][2 * nfp + 1], a[mf], bf[nfp][1], bf[nfp][3]);
            }
    }

    const int lr = lane >> 2;
    const int lc = lane & 3;
    #pragma unroll
    for (int mf = 0; mf < 4; mf++) {
        int row = o0 + wm * 64 + mf * 16 + lr;
        #pragma unroll
        for (int nf = 0; nf < 4; nf++) {
            int col = d0 + wn * 32 + nf * 8 + lc * 2;
            const float* bwp0 = base_w + (size_t)row * DIN + col;
            const float* bwp1 = base_w + (size_t)(row + 8) * DIN + col;
            __half2 h0 = __floats2half2_rn(acc[mf][nf][0] + bwp0[0],
                                           acc[mf][nf][1] + bwp0[1]);
            __half2 h1 = __floats2half2_rn(acc[mf][nf][2] + bwp1[0],
                                           acc[mf][nf][3] + bwp1[1]);
            *(__half2*)(g_wh + ((size_t)b * DOUT + row) * DIN + col)     = h0;
            *(__half2*)(g_wh + ((size_t)b * DOUT + row + 8) * DIN + col) = h1;
        }
    }
}

// ---------------------------------------------------------------------------
// Main GEMM: out[b] = x[b] @ W_eff[b]^T + base_b.
// fp16-accumulate m16n8k16 (2x legacy-pipe rate), K=32 chunks promoted to fp32.
// CTA 128x256, BK=64, 4-stage cp.async, XOR-swizzled smem, ldmatrix.x4.
// ---------------------------------------------------------------------------
#define BM 128
#define BN 256
#define BK 64
#define NKT (DIN / BK)
#define STAGES 4
#define A_STAGE_BYTES (BM * 128)
#define B_STAGE_BYTES (BN * 128)
#define STAGE_BYTES (A_STAGE_BYTES + B_STAGE_BYTES)
#define SMEM_BYTES (STAGES * STAGE_BYTES + 1024)

__global__ __launch_bounds__(256, 1) void gemm_kernel(
    const float* __restrict__ base_b,
    float* __restrict__ out)
{
    extern __shared__ char dsmem_raw[];
    const uint32_t dyn = (smem_u32(dsmem_raw) + 1023u) & ~1023u;

    const int tid  = threadIdx.x;
    const int lane = tid & 31;
    const int wid  = tid >> 5;
    const int wm   = wid >> 2;
    const int wn   = wid & 3;

    const int b  = blockIdx.z;
    const int mt = blockIdx.y;
    const int nt = blockIdx.x;

    const __half* Ag = g_xh + ((size_t)b * SEQ  + (size_t)mt * BM) * DIN;
    const __half* Bg = g_wh + ((size_t)b * DOUT + (size_t)nt * BN) * DIN;

    const int mi    = lane >> 3;
    const int rl    = lane & 7;
    const int half8 = (mi & 1) << 3;
    const int gsel  = mi >> 1;
    const int rA    = wm * 64 + half8 + rl;
    const int rB    = wn * 64 + half8 + rl;
    const uint32_t swA = (uint32_t)(rA & 7);
    const uint32_t swB = (uint32_t)(rB & 7);

    float acc[4][8][4];
    #pragma unroll
    for (int mf = 0; mf < 4; mf++)
        #pragma unroll
        for (int nf = 0; nf < 8; nf++)
            #pragma unroll
            for (int k = 0; k < 4; k++) acc[mf][nf][k] = 0.0f;

    auto load_stage = [&](int st) {
        const uint32_t base = dyn + (uint32_t)(st & (STAGES - 1)) * STAGE_BYTES;
        const int koff = st * BK;
        #pragma unroll
        for (int i = 0; i < 4; i++) {
            int c = tid + i * 256;
            int row = c >> 3, q = c & 7;
            uint32_t dst = base + (uint32_t)(row * 128) + (uint32_t)((q ^ (row & 7)) << 4);
            cp_async16(dst, Ag + (size_t)row * DIN + koff + q * 8);
        }
        #pragma unroll
        for (int i = 0; i < 8; i++) {
            int c = tid + i * 256;
            int row = c >> 3, q = c & 7;
            uint32_t dst = base + A_STAGE_BYTES + (uint32_t)(row * 128)
                         + (uint32_t)((q ^ (row & 7)) << 4);
            cp_async16(dst, Bg + (size_t)row * DIN + koff + q * 8);
        }
        cp_commit();
    };

    load_stage(0);
    load_stage(1);
    load_stage(2);

    for (int kt = 0; kt < NKT; kt++) {
        cp_wait<STAGES - 2>();
        __syncthreads();

        if (kt + STAGES - 1 < NKT) load_stage(kt + STAGES - 1);
        else                       cp_commit();

        const uint32_t At = dyn + (uint32_t)(kt & (STAGES - 1)) * STAGE_BYTES;
        const uint32_t Bt = At + A_STAGE_BYTES;
        const uint32_t aBase = At + (uint32_t)(rA * 128);
        const uint32_t bBase = Bt + (uint32_t)(rB * 128);

        // 2 chunks of 2 k16-steps each; fp16 accum inside chunk, fp32 promote after.
        #pragma unroll
        for (int ch2 = 0; ch2 < 2; ch2++) {
            uint32_t a[2][4][4], bf[2][4][4];
            #pragma unroll
            for (int s = 0; s < 2; s++) {
                const int ks = ch2 * 2 + s;
                #pragma unroll
                for (int mf = 0; mf < 4; mf++)
                    ldmatrix_x4(a[s][mf], aBase + (uint32_t)(mf * 2048)
                                     + ((((uint32_t)(2 * ks) + gsel) ^ swA) << 4));
                #pragma unroll
                for (int nfp = 0; nfp < 4; nfp++)
                    ldmatrix_x4(bf[s][nfp], bBase + (uint32_t)(nfp * 2048)
                                       + ((((uint32_t)(2 * ks) + gsel) ^ swB) << 4));
            }
            #pragma unroll
            for (int mf = 0; mf < 4; mf++)
                #pragma unroll
                for (int nfp = 0; nfp < 4; nfp++)
                    #pragma unroll
                    for (int h = 0; h < 2; h++) {
                        uint32_t d0, d1;
                        mma_h16_z  (d0, d1, a[0][mf], bf[0][nfp][h], bf[0][nfp][h + 2]);
                        mma_h16_acc(d0, d1, a[1][mf], bf[1][nfp][h], bf[1][nfp][h + 2]);
                        float* ac = acc[mf][2 * nfp + h];
                        float2 lo = __half22float2(*(__half2*)&d0);
                        float2 hi = __half22float2(*(__half2*)&d1);
                        ac[0] += lo.x; ac[1] += lo.y;
                        ac[2] += hi.x; ac[3] += hi.y;
                    }
        }
    }

    const int lr = lane >> 2;
    const int lc = lane & 3;
    float* Cg = out + ((size_t)b * SEQ + (size_t)mt * BM) * DOUT + (size_t)nt * BN;
    const float* bias = base_b + (size_t)nt * BN;

    #pragma unroll
    for (int mf = 0; mf < 4; mf++) {
        int row = wm * 64 + mf * 16 + lr;
        #pragma unroll
        for (int nf = 0; nf < 8; nf++) {
            int col = wn * 64 + nf * 8 + lc * 2;
            float b0 = bias[col], b1 = bias[col + 1];
            float2 r0, r1;
            r0.x = acc[mf][nf][0] + b0;
            r0.y = acc[mf][nf][1] + b1;
            r1.x = acc[mf][nf][2] + b0;
            r1.y = acc[mf][nf][3] + b1;
            *(float2*)(Cg + (size_t)row * DOUT + col)       = r0;
            *(float2*)(Cg + (size_t)(row + 8) * DOUT + col) = r1;
        }
    }
}

// ---------------------------------------------------------------------------
// Launch
// ---------------------------------------------------------------------------
extern "C" void kernel_launch(void* const* d_in, const int* in_sizes, int n_in,
                              void* d_out, int out_size) {
    const float* x      = (const float*)d_in[0];
    const float* mem_f  = (const float*)d_in[1];
    const float* mem_m  = (const float*)d_in[2];
    const float* mem_s  = (const float*)d_in[3];
    const float* base_w = (const float*)d_in[4];
    const float* base_b = (const float*)d_in[5];
    const float* pd_w   = (const float*)d_in[6];
    const float* pu_w   = (const float*)d_in[7];
    // d_in[8..11]: gate network weights — mathematically dead
    // (softmax sums to 1, mean over the 3-way axis == 1/3 exactly).
    float* out = (float*)d_out;

    conv_x_kernel<<<(B_BATCH * SEQ * DIN) / (256 * 4), 256>>>((const float4*)x);

    cudaFuncSetAttribute(prep_mma_kernel,
                         cudaFuncAttributeMaxDynamicSharedMemorySize, PREP_SMEM_BYTES);
    prep_mma_kernel<<<dim3(DIN / 128, DOUT / 128, B_BATCH), 256, PREP_SMEM_BYTES>>>(
        base_w, pd_w, pu_w, mem_f, mem_m, mem_s);

    cudaFuncSetAttribute(gemm_kernel,
                         cudaFuncAttributeMaxDynamicSharedMemorySize, SMEM_BYTES);
    gemm_kernel<<<dim3(DOUT / BN, SEQ / BM, B_BATCH), 256, SMEM_BYTES>>>(
        base_b, out);
}

// round 6
// speedup vs baseline: 1.1864x; 1.1864x over previous
#include <cuda_runtime.h>
#include <cuda_fp16.h>
#include <stdint.h>

// Problem constants
#define B_BATCH 8
#define SEQ     4096
#define DIN     1024
#define DOUT    1024
#define RTOT    104

// Scratch: fp16 folded weights (16 MB)
__device__ __half g_wh[(size_t)B_BATCH * DOUT * DIN];

__device__ __forceinline__ uint32_t smem_u32(const void* p) {
    return (uint32_t)__cvta_generic_to_shared(p);
}
__device__ __forceinline__ void cp_async16(uint32_t saddr, const void* gptr) {
    asm volatile("cp.async.cg.shared.global [%0], [%1], 16;\n" :: "r"(saddr), "l"(gptr));
}
__device__ __forceinline__ void cp_commit() {
    asm volatile("cp.async.commit_group;\n");
}
template <int N>
__device__ __forceinline__ void cp_wait() {
    asm volatile("cp.async.wait_group %0;\n" :: "n"(N));
}
__device__ __forceinline__ void ldmatrix_x4(uint32_t r[4], uint32_t addr) {
    asm volatile("ldmatrix.sync.aligned.m8n8.x4.shared.b16 {%0,%1,%2,%3}, [%4];"
                 : "=r"(r[0]), "=r"(r[1]), "=r"(r[2]), "=r"(r[3]) : "r"(addr));
}
__device__ __forceinline__ void ldmatrix_x4_trans(uint32_t r[4], uint32_t addr) {
    asm volatile("ldmatrix.sync.aligned.m8n8.x4.trans.shared.b16 {%0,%1,%2,%3}, [%4];"
                 : "=r"(r[0]), "=r"(r[1]), "=r"(r[2]), "=r"(r[3]) : "r"(addr));
}
__device__ __forceinline__ void mma_f16(float c[4], const uint32_t a[4],
                                        uint32_t b0, uint32_t b1) {
    asm volatile("mma.sync.aligned.m16n8k16.row.col.f32.f16.f16.f32 "
                 "{%0,%1,%2,%3}, {%4,%5,%6,%7}, {%8,%9}, {%0,%1,%2,%3};\n"
                 : "+f"(c[0]), "+f"(c[1]), "+f"(c[2]), "+f"(c[3])
                 : "r"(a[0]), "r"(a[1]), "r"(a[2]), "r"(a[3]), "r"(b0), "r"(b1));
}

// ---------------------------------------------------------------------------
// Tensor-core prep (unchanged from round 4): W_eff[b] = base_w + pu_mod[b] @ pd.
// ---------------------------------------------------------------------------
#define KP 112
#define PSA 120
#define PSB 136
#define PREP_A_HALVES (128 * PSA)
#define PREP_SMEM_BYTES ((128 * PSA + KP * PSB) * 2)

__global__ __launch_bounds__(256) void prep_mma_kernel(
    const float* __restrict__ base_w,
    const float* __restrict__ pd_w,
    const float* __restrict__ pu_w,
    const float* __restrict__ mem_f,
    const float* __restrict__ mem_m,
    const float* __restrict__ mem_s)
{
    extern __shared__ __half psm[];
    __half* As = psm;
    __half* Bs = psm + PREP_A_HALVES;
    __shared__ float s_fac[KP];

    const int b  = blockIdx.z;
    const int o0 = blockIdx.y * 128;
    const int d0 = blockIdx.x * 128;
    const int tid = threadIdx.x;

    if (tid < KP) {
        float f = 0.0f;
        int r = tid;
        if (r < RTOT) {
            float memv;
            if (r < 8)       memv = mem_f[b * 8  + r];
            else if (r < 40) memv = mem_m[b * 32 + (r - 8)];
            else             memv = mem_s[b * 64 + (r - 40)];
            f = (1.0f + memv) * (1.0f / 3.0f);
        }
        s_fac[r] = f;
    }
    __syncthreads();

    for (int i = tid; i < 128 * KP; i += 256) {
        int o = i / KP, r = i - o * KP;
        float v = (r < RTOT) ? pu_w[(size_t)(o0 + o) * RTOT + r] * s_fac[r] : 0.0f;
        As[o * PSA + r] = __float2half(v);
    }
    for (int i = tid; i < KP * 128; i += 256) {
        int r = i >> 7, d = i & 127;
        float v = (r < RTOT) ? pd_w[(size_t)r * DIN + d0 + d] : 0.0f;
        Bs[r * PSB + d] = __float2half(v);
    }
    __syncthreads();

    const int lane = tid & 31;
    const int wid  = tid >> 5;
    const int wm   = wid >> 2;
    const int wn   = wid & 3;

    const int mi = lane >> 3;
    const int rl = lane & 7;
    const int aRow = wm * 64 + ((mi & 1) << 3) + rl;
    const int gsel = mi >> 1;
    const int bK   = ((mi >> 1) << 3) + rl;
    const int bN   = wn * 32 + ((mi & 1) << 3);

    const uint32_t sA = smem_u32(As);
    const uint32_t sB = smem_u32(Bs);

    float acc[4][4][4];
    #pragma unroll
    for (int mf = 0; mf < 4; mf++)
        #pragma unroll
        for (int nf = 0; nf < 4; nf++)
            #pragma unroll
            for (int k = 0; k < 4; k++) acc[mf][nf][k] = 0.0f;

    #pragma unroll
    for (int ks = 0; ks < KP / 16; ks++) {
        uint32_t a[4][4], bf[2][4];
        #pragma unroll
        for (int mf = 0; mf < 4; mf++)
            ldmatrix_x4(a[mf],
                sA + (uint32_t)(((aRow + mf * 16) * PSA + ks * 16 + gsel * 8) * 2));
        #pragma unroll
        for (int nfp = 0; nfp < 2; nfp++)
            ldmatrix_x4_trans(bf[nfp],
                sB + (uint32_t)(((ks * 16 + bK) * PSB + bN + nfp * 16) * 2));
        #pragma unroll
        for (int mf = 0; mf < 4; mf++)
            #pragma unroll
            for (int nfp = 0; nfp < 2; nfp++) {
                mma_f16(acc[mf][2 * nfp + 0], a[mf], bf[nfp][0], bf[nfp][2]);
                mma_f16(acc[mf][2 * nfp + 1], a[mf], bf[nfp][1], bf[nfp][3]);
            }
    }

    const int lr = lane >> 2;
    const int lc = lane & 3;
    #pragma unroll
    for (int mf = 0; mf < 4; mf++) {
        int row = o0 + wm * 64 + mf * 16 + lr;
        #pragma unroll
        for (int nf = 0; nf < 4; nf++) {
            int col = d0 + wn * 32 + nf * 8 + lc * 2;
            const float* bwp0 = base_w + (size_t)row * DIN + col;
            const float* bwp1 = base_w + (size_t)(row + 8) * DIN + col;
            __half2 h0 = __floats2half2_rn(acc[mf][nf][0] + bwp0[0],
                                           acc[mf][nf][1] + bwp0[1]);
            __half2 h1 = __floats2half2_rn(acc[mf][nf][2] + bwp1[0],
                                           acc[mf][nf][3] + bwp1[1]);
            *(__half2*)(g_wh + ((size_t)b * DOUT + row) * DIN + col)     = h0;
            *(__half2*)(g_wh + ((size_t)b * DOUT + row + 8) * DIN + col) = h1;
        }
    }
}

// ---------------------------------------------------------------------------
// Main GEMM: out[b] = x[b] @ W_eff[b]^T + base_b.
// fp16 m16n8k16 (fp32 accum), CTA 128x256, BK=64, 4-slot smem ring.
// A: LDG fp32 -> cvt -> swizzled STS fp16 (fused x-conversion, 3-iter prefetch).
// B: cp.async fp16, 4-stage. XOR-swizzled smem, ldmatrix.x4 feeds.
// ---------------------------------------------------------------------------
#define BM 128
#define BN 256
#define BK 64
#define NKT (DIN / BK)
#define STAGES 4
#define A_STAGE_BYTES (BM * 128)
#define B_STAGE_BYTES (BN * 128)
#define STAGE_BYTES (A_STAGE_BYTES + B_STAGE_BYTES)
#define SMEM_BYTES (STAGES * STAGE_BYTES + 1024)

__global__ __launch_bounds__(256, 1) void gemm_kernel(
    const float* __restrict__ x,
    const float* __restrict__ base_b,
    float* __restrict__ out)
{
    extern __shared__ char dsmem_raw[];
    const uint32_t dyn = (smem_u32(dsmem_raw) + 1023u) & ~1023u;

    const int tid  = threadIdx.x;
    const int lane = tid & 31;
    const int wid  = tid >> 5;
    const int wm   = wid >> 2;
    const int wn   = wid & 3;

    const int b  = blockIdx.z;
    const int mt = blockIdx.y;
    const int nt = blockIdx.x;

    const float* Ag = x    + ((size_t)b * SEQ  + (size_t)mt * BM) * DIN;
    const __half* Bg = g_wh + ((size_t)b * DOUT + (size_t)nt * BN) * DIN;

    // Per-thread A chunk geometry (4 chunks of 8 elements)
    int arow[4], aq[4];
    uint32_t asts[4];
    #pragma unroll
    for (int i = 0; i < 4; i++) {
        int c = tid + i * 256;
        arow[i] = c >> 3;
        aq[i]   = c & 7;
        asts[i] = (uint32_t)(arow[i] * 128) + (uint32_t)((aq[i] ^ (arow[i] & 7)) << 4);
    }

    const int mi    = lane >> 3;
    const int rl    = lane & 7;
    const int half8 = (mi & 1) << 3;
    const int gsel  = mi >> 1;
    const int rA    = wm * 64 + half8 + rl;
    const int rB    = wn * 64 + half8 + rl;
    const uint32_t swA = (uint32_t)(rA & 7);
    const uint32_t swB = (uint32_t)(rB & 7);

    float acc[4][8][4];
    #pragma unroll
    for (int mf = 0; mf < 4; mf++)
        #pragma unroll
        for (int nf = 0; nf < 8; nf++)
            #pragma unroll
            for (int k = 0; k < 4; k++) acc[mf][nf][k] = 0.0f;

    auto ldgA = [&](int st, float4 v[4][2]) {
        const int koff = st * BK;
        #pragma unroll
        for (int i = 0; i < 4; i++) {
            const float4* p = (const float4*)(Ag + (size_t)arow[i] * DIN + koff + aq[i] * 8);
            v[i][0] = p[0];
            v[i][1] = p[1];
        }
    };
    auto stsA = [&](int st, const float4 v[4][2]) {
        const uint32_t base = dyn + (uint32_t)(st & (STAGES - 1)) * STAGE_BYTES;
        #pragma unroll
        for (int i = 0; i < 4; i++) {
            __half2 h0 = __floats2half2_rn(v[i][0].x, v[i][0].y);
            __half2 h1 = __floats2half2_rn(v[i][0].z, v[i][0].w);
            __half2 h2 = __floats2half2_rn(v[i][1].x, v[i][1].y);
            __half2 h3 = __floats2half2_rn(v[i][1].z, v[i][1].w);
            uint4 u;
            u.x = *(uint32_t*)&h0; u.y = *(uint32_t*)&h1;
            u.z = *(uint32_t*)&h2; u.w = *(uint32_t*)&h3;
            asm volatile("st.shared.v4.b32 [%0], {%1,%2,%3,%4};\n"
                         :: "r"(base + asts[i]), "r"(u.x), "r"(u.y), "r"(u.z), "r"(u.w));
        }
    };
    auto loadB = [&](int st) {
        const uint32_t base = dyn + (uint32_t)(st & (STAGES - 1)) * STAGE_BYTES
                            + A_STAGE_BYTES;
        const int koff = st * BK;
        #pragma unroll
        for (int i = 0; i < 8; i++) {
            int c = tid + i * 256;
            int row = c >> 3, q = c & 7;
            uint32_t dst = base + (uint32_t)(row * 128) + (uint32_t)((q ^ (row & 7)) << 4);
            cp_async16(dst, Bg + (size_t)row * DIN + koff + q * 8);
        }
        cp_commit();
    };

    // Prologue: stages 0..2 (A direct LDG->STS, B cp.async)
    {
        float4 v[4][2];
        #pragma unroll
        for (int st = 0; st < 3; st++) {
            ldgA(st, v);
            stsA(st, v);
            loadB(st);
        }
    }

    for (int kt = 0; kt < NKT; kt++) {
        cp_wait<2>();           // B(kt) landed
        __syncthreads();        // A(kt) STS + B(kt) visible to all; slot kt-1 free

        // Prefetch A(kt+3) into registers (latency hides under MMA block)
        float4 v[4][2];
        const bool pf = (kt + 3 < NKT);
        if (pf) ldgA(kt + 3, v);

        const uint32_t At = dyn + (uint32_t)(kt & (STAGES - 1)) * STAGE_BYTES;
        const uint32_t Bt = At + A_STAGE_BYTES;
        const uint32_t aBase = At + (uint32_t)(rA * 128);
        const uint32_t bBase = Bt + (uint32_t)(rB * 128);

        #pragma unroll
        for (int ks = 0; ks < 4; ks++) {
            uint32_t a[4][4], bf[4][4];
            #pragma unroll
            for (int mf = 0; mf < 4; mf++)
                ldmatrix_x4(a[mf], aBase + (uint32_t)(mf * 2048)
                                 + ((((uint32_t)(2 * ks) + gsel) ^ swA) << 4));
            #pragma unroll
            for (int nfp = 0; nfp < 4; nfp++)
                ldmatrix_x4(bf[nfp], bBase + (uint32_t)(nfp * 2048)
                                   + ((((uint32_t)(2 * ks) + gsel) ^ swB) << 4));
            #pragma unroll
            for (int mf = 0; mf < 4; mf++)
                #pragma unroll
                for (int nfp = 0; nfp < 4; nfp++) {
                    mma_f16(acc[mf][2 * nfp + 0], a[mf], bf[nfp][0], bf[nfp][2]);
                    mma_f16(acc[mf][2 * nfp + 1], a[mf], bf[nfp][1], bf[nfp][3]);
                }
        }

        // Store prefetched A and kick B for stage kt+3
        if (pf) {
            stsA(kt + 3, v);
            loadB(kt + 3);
        } else {
            cp_commit();        // empty group keeps wait math uniform
        }
    }

    const int lr = lane >> 2;
    const int lc = lane & 3;
    float* Cg = out + ((size_t)b * SEQ + (size_t)mt * BM) * DOUT + (size_t)nt * BN;
    const float* bias = base_b + (size_t)nt * BN;

    #pragma unroll
    for (int mf = 0; mf < 4; mf++) {
        int row = wm * 64 + mf * 16 + lr;
        #pragma unroll
        for (int nf = 0; nf < 8; nf++) {
            int col = wn * 64 + nf * 8 + lc * 2;
            float b0 = bias[col], b1 = bias[col + 1];
            float2 r0, r1;
            r0.x = acc[mf][nf][0] + b0;
            r0.y = acc[mf][nf][1] + b1;
            r1.x = acc[mf][nf][2] + b0;
            r1.y = acc[mf][nf][3] + b1;
            *(float2*)(Cg + (size_t)row * DOUT + col)       = r0;
            *(float2*)(Cg + (size_t)(row + 8) * DOUT + col) = r1;
        }
    }
}

// ---------------------------------------------------------------------------
// Launch
// ---------------------------------------------------------------------------
extern "C" void kernel_launch(void* const* d_in, const int* in_sizes, int n_in,
                              void* d_out, int out_size) {
    const float* x      = (const float*)d_in[0];
    const float* mem_f  = (const float*)d_in[1];
    const float* mem_m  = (const float*)d_in[2];
    const float* mem_s  = (const float*)d_in[3];
    const float* base_w = (const float*)d_in[4];
    const float* base_b = (const float*)d_in[5];
    const float* pd_w   = (const float*)d_in[6];
    const float* pu_w   = (const float*)d_in[7];
    // d_in[8..11]: gate network weights — mathematically dead
    // (softmax sums to 1, mean over the 3-way axis == 1/3 exactly).
    float* out = (float*)d_out;

    cudaFuncSetAttribute(prep_mma_kernel,
                         cudaFuncAttributeMaxDynamicSharedMemorySize, PREP_SMEM_BYTES);
    prep_mma_kernel<<<dim3(DIN / 128, DOUT / 128, B_BATCH), 256, PREP_SMEM_BYTES>>>(
        base_w, pd_w, pu_w, mem_f, mem_m, mem_s);

    cudaFuncSetAttribute(gemm_kernel,
                         cudaFuncAttributeMaxDynamicSharedMemorySize, SMEM_BYTES);
    gemm_kernel<<<dim3(DOUT / BN, SEQ / BM, B_BATCH), 256, SMEM_BYTES>>>(
        x, base_b, out);
}